// round 5
// baseline (speedup 1.0000x reference)
#include <cuda_runtime.h>

#define RESN  320
#define BATCH 32
#define HW    (RESN*RESN)

#define LANES  80
#define NROWS  8
#define SPITCH 321   // float2 pitch (pad to avoid bank conflicts on transposed access)

// Scratch (allocation-free rule: __device__ globals)
__device__ float2 g_grid[BATCH*HW];   // 26 MB
__device__ float2 g_tmp [BATCH*HW];   // 26 MB

// ---------------------------------------------------------------------------
// complex helpers
// ---------------------------------------------------------------------------
__device__ __forceinline__ float2 cadd(float2 a, float2 b){ return make_float2(a.x+b.x, a.y+b.y); }
__device__ __forceinline__ float2 csub(float2 a, float2 b){ return make_float2(a.x-b.x, a.y-b.y); }
__device__ __forceinline__ float2 cmul(float2 a, float2 b){
    return make_float2(a.x*b.x - a.y*b.y, a.x*b.y + a.y*b.x);
}
__device__ __forceinline__ float2 cjmul(float2 a){ return make_float2(-a.y, a.x); } // i*a
__device__ __forceinline__ float2 twid(float frac){ // e^{+2*pi*i*frac}
    float s, c;
    sincospif(2.0f*frac, &s, &c);
    return make_float2(c, s);
}

// ---------------------------------------------------------------------------
// Kernel 1: gridding (interp + adjoint-scatter collapsed to a fixed stencil)
// Also applies the ifftshift pre-twist (-1)^(a+bx) and the 1/16 scale.
// ---------------------------------------------------------------------------
__global__ void grid_kernel(const float2* __restrict__ in)
{
    int idx = blockIdx.x * blockDim.x + threadIdx.x;
    if (idx >= HW) return;
    int b  = blockIdx.y;
    int a  = idx / RESN;   // iy (grid row)
    int bx = idx % RESN;   // ix (grid col)
    const float2* c = in + (size_t)b * HW;

    float sr = 0.f, si = 0.f;
    #pragma unroll
    for (int di = 0; di < 2; ++di) {
        int I = bx + di;
        if (I >= RESN) continue;
        bool skipI = (I >= 140 && I <= 170);
        #pragma unroll
        for (int dj = 0; dj < 2; ++dj) {
            int J = a + dj;
            if (J >= RESN) continue;
            if (skipI || (J >= 120 && J <= 160)) continue;   // skipped trajectory point
            // 4-corner sum for point (I,J): ix in {I-1,I}, iy in {J-1,J}
            #pragma unroll
            for (int dx = -1; dx <= 0; ++dx) {
                int ix = I + dx;
                if (ix < 0) continue;
                #pragma unroll
                for (int dy = -1; dy <= 0; ++dy) {
                    int iy = J + dy;
                    if (iy < 0) continue;
                    float2 v = __ldg(&c[iy*RESN + ix]);
                    sr += v.x; si += v.y;
                }
            }
        }
    }
    if (idx == 0) {   // all 21769 skipped points hit corner (0,0) with weight 1/16
        float2 v = __ldg(&c[0]);
        sr += 21769.0f * v.x;
        si += 21769.0f * v.y;
    }
    float s = ((a + bx) & 1) ? -0.0625f : 0.0625f;
    g_grid[(size_t)b * HW + idx] = make_float2(sr * s, si * s);
}

// ---------------------------------------------------------------------------
// 320-point inverse (unnormalized) FFT, Stockham autosort, radices 5,4,4,4.
// Input natural order in A; result natural order in A. B is scratch.
// ---------------------------------------------------------------------------
template<int Ns>
__device__ __forceinline__ void radix4_stage(const float2* __restrict__ src,
                                             float2* __restrict__ dst, int j)
{
    float2 v0 = src[j];
    float2 v1 = src[j + 80];
    float2 v2 = src[j + 160];
    float2 v3 = src[j + 240];
    int m = j % Ns;
    constexpr float inv = 1.0f / (4 * Ns);
    v1 = cmul(v1, twid((float)m       * inv));
    v2 = cmul(v2, twid((float)(2*m)   * inv));
    v3 = cmul(v3, twid((float)(3*m)   * inv));
    float2 t0 = cadd(v0, v2), t1 = csub(v0, v2);
    float2 t2 = cadd(v1, v3), t3 = csub(v1, v3);
    float2 it3 = cjmul(t3);
    int d = (j / Ns) * (4 * Ns) + m;
    dst[d]          = cadd(t0, t2);
    dst[d + Ns]     = cadd(t1, it3);
    dst[d + 2 * Ns] = csub(t0, t2);
    dst[d + 3 * Ns] = csub(t1, it3);
}

__device__ __forceinline__ void fft320_inv(float2* A, float2* B, int lane)
{
    // stage 1: radix-5, Ns=1, 64 butterflies, no twiddle. A -> B
    if (lane < 64) {
        float2 v0 = A[lane], v1 = A[lane+64], v2 = A[lane+128],
               v3 = A[lane+192], v4 = A[lane+256];
        const float c1 =  0.30901699437494745f, c2 = -0.80901699437494745f;
        const float s1 =  0.95105651629515353f, s2 =  0.58778525229247314f;
        float2 t1 = cadd(v1, v4), t2 = cadd(v2, v3);
        float2 t3 = csub(v1, v4), t4 = csub(v2, v3);
        float2 a1 = make_float2(v0.x + c1*t1.x + c2*t2.x, v0.y + c1*t1.y + c2*t2.y);
        float2 a2 = make_float2(v0.x + c2*t1.x + c1*t2.x, v0.y + c2*t1.y + c1*t2.y);
        float2 b1 = make_float2(s1*t3.x + s2*t4.x, s1*t3.y + s2*t4.y);
        float2 b2 = make_float2(s2*t3.x - s1*t4.x, s2*t3.y - s1*t4.y);
        float2 ib1 = cjmul(b1), ib2 = cjmul(b2);
        int d = lane * 5;
        B[d + 0] = make_float2(v0.x + t1.x + t2.x, v0.y + t1.y + t2.y);
        B[d + 1] = cadd(a1, ib1);
        B[d + 2] = cadd(a2, ib2);
        B[d + 3] = csub(a2, ib2);
        B[d + 4] = csub(a1, ib1);
    }
    __syncthreads();
    radix4_stage<5 >(B, A, lane);  __syncthreads();
    radix4_stage<20>(A, B, lane);  __syncthreads();
    radix4_stage<80>(B, A, lane);  __syncthreads();
    // result in A, natural order
}

// ---------------------------------------------------------------------------
// Kernel 2: row FFTs of g_grid, store transposed into g_tmp.
//   g_tmp[b][n][m] = IFFT_n(g_grid[b][m][:])[n]
// ---------------------------------------------------------------------------
__global__ __launch_bounds__(NROWS*LANES) void fft_rows_kernel()
{
    __shared__ float2 sA[NROWS * SPITCH];
    __shared__ float2 sB[NROWS * SPITCH];
    int tid  = threadIdx.x;
    int rl   = tid / LANES;
    int lane = tid - rl * LANES;
    int rowg = blockIdx.x * NROWS + rl;         // = b*320 + m
    const float2* p = g_grid + (size_t)rowg * RESN;
    float2* A = sA + rl * SPITCH;
    float2* B = sB + rl * SPITCH;
    #pragma unroll
    for (int k = 0; k < 4; ++k) A[lane + 80*k] = p[lane + 80*k];
    __syncthreads();
    fft320_inv(A, B, lane);
    // transposed store (8-wide contiguous chunks in m)
    int b  = (blockIdx.x * NROWS) / RESN;
    int m0 = (blockIdx.x * NROWS) % RESN;
    for (int i = tid; i < NROWS * RESN; i += NROWS * LANES) {
        int n  = i >> 3;
        int ml = i & 7;
        g_tmp[((size_t)b * RESN + n) * RESN + m0 + ml] = sA[ml * SPITCH + n];
    }
}

// ---------------------------------------------------------------------------
// Kernel 3: column FFTs (rows of g_tmp), apply fftshift post-twist (-1)^(m+n),
// split into planar real/imag output (B,1,2,H,W).
// ---------------------------------------------------------------------------
__global__ __launch_bounds__(NROWS*LANES) void fft_cols_kernel(float* __restrict__ out)
{
    __shared__ float2 sA[NROWS * SPITCH];
    __shared__ float2 sB[NROWS * SPITCH];
    int tid  = threadIdx.x;
    int rl   = tid / LANES;
    int lane = tid - rl * LANES;
    int rowg = blockIdx.x * NROWS + rl;         // = b*320 + n
    const float2* p = g_tmp + (size_t)rowg * RESN;
    float2* A = sA + rl * SPITCH;
    float2* B = sB + rl * SPITCH;
    #pragma unroll
    for (int k = 0; k < 4; ++k) A[lane + 80*k] = p[lane + 80*k];
    __syncthreads();
    fft320_inv(A, B, lane);
    int b  = (blockIdx.x * NROWS) / RESN;
    int n0 = (blockIdx.x * NROWS) % RESN;
    float* outb = out + (size_t)b * 2 * HW;
    for (int i = tid; i < NROWS * RESN; i += NROWS * LANES) {
        int m  = i >> 3;
        int nl = i & 7;
        float2 v = sA[nl * SPITCH + m];
        float sg = ((m + n0 + nl) & 1) ? -1.0f : 1.0f;
        outb[m * RESN + n0 + nl]      = v.x * sg;   // real plane
        outb[HW + m * RESN + n0 + nl] = v.y * sg;   // imag plane
    }
}

// ---------------------------------------------------------------------------
extern "C" void kernel_launch(void* const* d_in, const int* in_sizes, int n_in,
                              void* d_out, int out_size)
{
    const float2* in = (const float2*)d_in[0];   // k_space_input (B,1,320,320,2)
    float* out = (float*)d_out;                  // (B,1,2,320,320) float32
    (void)in_sizes; (void)n_in; (void)out_size;

    dim3 g1((HW + 255) / 256, BATCH);
    grid_kernel<<<g1, 256>>>(in);
    fft_rows_kernel<<<BATCH * RESN / NROWS, NROWS * LANES>>>();
    fft_cols_kernel<<<BATCH * RESN / NROWS, NROWS * LANES>>>(out);
}

// round 6
// speedup vs baseline: 1.2014x; 1.2014x over previous
#include <cuda_runtime.h>

#define RESN  320
#define BATCH 32
#define HW    (RESN*RESN)

#define LANES  80
#define NROWS  8
#define SPITCH 321   // float2 pitch (pad to avoid bank conflicts on transposed access)

// Scratch (allocation-free rule: __device__ globals)
__device__ float2 g_tmp[BATCH*HW];   // 26 MB intermediate (after row FFTs, transposed)

// ---------------------------------------------------------------------------
// complex helpers
// ---------------------------------------------------------------------------
__device__ __forceinline__ float2 cadd(float2 a, float2 b){ return make_float2(a.x+b.x, a.y+b.y); }
__device__ __forceinline__ float2 csub(float2 a, float2 b){ return make_float2(a.x-b.x, a.y-b.y); }
__device__ __forceinline__ float2 cmul(float2 a, float2 b){
    return make_float2(a.x*b.x - a.y*b.y, a.x*b.y + a.y*b.x);
}
__device__ __forceinline__ float2 cjmul(float2 a){ return make_float2(-a.y, a.x); } // i*a
__device__ __forceinline__ float2 twid(float frac){ // e^{+2*pi*i*frac}
    float s, c;
    sincospif(2.0f*frac, &s, &c);
    return make_float2(c, s);
}

// ---------------------------------------------------------------------------
// 320-point inverse (unnormalized) FFT, Stockham autosort, radices 5,4,4,4.
// Input natural order in A; result natural order in A. B is scratch.
// ---------------------------------------------------------------------------
template<int Ns>
__device__ __forceinline__ void radix4_stage(const float2* __restrict__ src,
                                             float2* __restrict__ dst, int j)
{
    float2 v0 = src[j];
    float2 v1 = src[j + 80];
    float2 v2 = src[j + 160];
    float2 v3 = src[j + 240];
    int m = j % Ns;
    constexpr float inv = 1.0f / (4 * Ns);
    v1 = cmul(v1, twid((float)m       * inv));
    v2 = cmul(v2, twid((float)(2*m)   * inv));
    v3 = cmul(v3, twid((float)(3*m)   * inv));
    float2 t0 = cadd(v0, v2), t1 = csub(v0, v2);
    float2 t2 = cadd(v1, v3), t3 = csub(v1, v3);
    float2 it3 = cjmul(t3);
    int d = (j / Ns) * (4 * Ns) + m;
    dst[d]          = cadd(t0, t2);
    dst[d + Ns]     = cadd(t1, it3);
    dst[d + 2 * Ns] = csub(t0, t2);
    dst[d + 3 * Ns] = csub(t1, it3);
}

__device__ __forceinline__ void fft320_inv(float2* A, float2* B, int lane)
{
    // stage 1: radix-5, Ns=1, 64 butterflies, no twiddle. A -> B
    if (lane < 64) {
        float2 v0 = A[lane], v1 = A[lane+64], v2 = A[lane+128],
               v3 = A[lane+192], v4 = A[lane+256];
        const float c1 =  0.30901699437494745f, c2 = -0.80901699437494745f;
        const float s1 =  0.95105651629515353f, s2 =  0.58778525229247314f;
        float2 t1 = cadd(v1, v4), t2 = cadd(v2, v3);
        float2 t3 = csub(v1, v4), t4 = csub(v2, v3);
        float2 a1 = make_float2(v0.x + c1*t1.x + c2*t2.x, v0.y + c1*t1.y + c2*t2.y);
        float2 a2 = make_float2(v0.x + c2*t1.x + c1*t2.x, v0.y + c2*t1.y + c1*t2.y);
        float2 b1 = make_float2(s1*t3.x + s2*t4.x, s1*t3.y + s2*t4.y);
        float2 b2 = make_float2(s2*t3.x - s1*t4.x, s2*t3.y - s1*t4.y);
        float2 ib1 = cjmul(b1), ib2 = cjmul(b2);
        int d = lane * 5;
        B[d + 0] = make_float2(v0.x + t1.x + t2.x, v0.y + t1.y + t2.y);
        B[d + 1] = cadd(a1, ib1);
        B[d + 2] = cadd(a2, ib2);
        B[d + 3] = csub(a2, ib2);
        B[d + 4] = csub(a1, ib1);
    }
    __syncthreads();
    radix4_stage<5 >(B, A, lane);  __syncthreads();
    radix4_stage<20>(A, B, lane);  __syncthreads();
    radix4_stage<80>(B, A, lane);  __syncthreads();
    // result in A, natural order
}

// ---------------------------------------------------------------------------
// Fused kernel: gridding stencil (separable, in smem) + row FFT + transposed
// store. Each block: batch b, 8 consecutive grid rows a0..a0+7.
// Loads input rows a0-1..a0+8 into sB (also the FFT scratch buffer).
// ---------------------------------------------------------------------------
__global__ __launch_bounds__(NROWS*LANES) void fused_rows_kernel(const float2* __restrict__ in)
{
    __shared__ float2 sA[NROWS * SPITCH];   // rowcomb -> grid rows -> FFT in/out
    __shared__ float2 sB[10 * SPITCH];      // input rows, later FFT scratch
    int tid  = threadIdx.x;
    int rl   = tid / LANES;
    int lane = tid - rl * LANES;
    int b  = blockIdx.x / (RESN / NROWS);
    int a0 = (blockIdx.x % (RESN / NROWS)) * NROWS;
    const float2* cb = in + (size_t)b * HW;

    // 1. load 10 input rows (iy = a0-1 .. a0+8), zero-padded at edges
    for (int i = tid; i < 10 * RESN; i += NROWS * LANES) {
        int r = i / RESN, col = i - r * RESN;
        int iy = a0 - 1 + r;
        float2 v = (iy >= 0 && iy < RESN) ? __ldg(&cb[iy * RESN + col])
                                          : make_float2(0.f, 0.f);
        sB[r * SPITCH + col] = v;
    }
    __syncthreads();

    // 2. vertical pass: rowcomb[a][i] = jm(a)*(row[a-1]+row[a]) + jm(a+1)*(row[a]+row[a+1])
    int a = a0 + rl;
    float c0 = (a >= 120 && a <= 160) ? 0.f : 1.f;                         // jm(a), a<=319 always
    float c1 = (a + 1 <= 319 && !(a + 1 >= 120 && a + 1 <= 160)) ? 1.f : 0.f; // jm(a+1)
    float c01 = c0 + c1;
    const float2* r0 = sB + rl * SPITCH;        // iy = a-1
    const float2* r1 = r0 + SPITCH;             // iy = a
    const float2* r2 = r1 + SPITCH;             // iy = a+1
    float2* A = sA + rl * SPITCH;
    #pragma unroll
    for (int k = 0; k < 4; ++k) {
        int i = lane + 80 * k;
        float2 v;
        v.x = c0 * r0[i].x + c01 * r1[i].x + c1 * r2[i].x;
        v.y = c0 * r0[i].y + c01 * r1[i].y + c1 * r2[i].y;
        A[i] = v;
    }
    __syncthreads();

    // 3. horizontal pass (read into regs, sync, write back — avoids RAW hazard)
    float2 vals[4];
    #pragma unroll
    for (int k = 0; k < 4; ++k) {
        int bx = lane + 80 * k;
        float2 rc  = A[bx];
        float2 rcm = (bx > 0)   ? A[bx - 1] : make_float2(0.f, 0.f);
        float2 rcp = (bx < 319) ? A[bx + 1] : make_float2(0.f, 0.f);
        float w0 = (bx >= 140 && bx <= 170) ? 0.f : 1.f;                      // im(bx)
        float w1 = (bx + 1 <= 319 && !(bx + 1 >= 140 && bx + 1 <= 170)) ? 1.f : 0.f;
        float vx = w0 * (rcm.x + rc.x) + w1 * (rc.x + rcp.x);
        float vy = w0 * (rcm.y + rc.y) + w1 * (rc.y + rcp.y);
        if (a0 == 0 && rl == 0 && bx == 0) {
            // all 21769 skipped trajectory points hit corner (0,0), weight 1/16
            float2 c00 = sB[1 * SPITCH + 0];   // input row iy=0, col 0
            vx += 21769.f * c00.x;
            vy += 21769.f * c00.y;
        }
        float s = ((a + bx) & 1) ? -0.0625f : 0.0625f;   // ifftshift pre-twist + 1/16
        vals[k] = make_float2(vx * s, vy * s);
    }
    __syncthreads();
    #pragma unroll
    for (int k = 0; k < 4; ++k) A[lane + 80 * k] = vals[k];
    __syncthreads();

    // 4. row FFT (sB rows reused as scratch — input no longer needed)
    fft320_inv(A, sB + rl * SPITCH, lane);

    // 5. transposed store: g_tmp[b][n][m]
    for (int i = tid; i < NROWS * RESN; i += NROWS * LANES) {
        int n  = i >> 3;
        int ml = i & 7;
        g_tmp[((size_t)b * RESN + n) * RESN + a0 + ml] = sA[ml * SPITCH + n];
    }
}

// ---------------------------------------------------------------------------
// Column FFTs (rows of g_tmp), fftshift post-twist (-1)^(m+n), planar output.
// ---------------------------------------------------------------------------
__global__ __launch_bounds__(NROWS*LANES) void fft_cols_kernel(float* __restrict__ out)
{
    __shared__ float2 sA[NROWS * SPITCH];
    __shared__ float2 sB[NROWS * SPITCH];
    int tid  = threadIdx.x;
    int rl   = tid / LANES;
    int lane = tid - rl * LANES;
    int rowg = blockIdx.x * NROWS + rl;         // = b*320 + n
    const float2* p = g_tmp + (size_t)rowg * RESN;
    float2* A = sA + rl * SPITCH;
    float2* B = sB + rl * SPITCH;
    #pragma unroll
    for (int k = 0; k < 4; ++k) A[lane + 80*k] = p[lane + 80*k];
    __syncthreads();
    fft320_inv(A, B, lane);
    int b  = (blockIdx.x * NROWS) / RESN;
    int n0 = (blockIdx.x * NROWS) % RESN;
    float* outb = out + (size_t)b * 2 * HW;
    for (int i = tid; i < NROWS * RESN; i += NROWS * LANES) {
        int m  = i >> 3;
        int nl = i & 7;
        float2 v = sA[nl * SPITCH + m];
        float sg = ((m + n0 + nl) & 1) ? -1.0f : 1.0f;
        outb[m * RESN + n0 + nl]      = v.x * sg;   // real plane
        outb[HW + m * RESN + n0 + nl] = v.y * sg;   // imag plane
    }
}

// ---------------------------------------------------------------------------
extern "C" void kernel_launch(void* const* d_in, const int* in_sizes, int n_in,
                              void* d_out, int out_size)
{
    const float2* in = (const float2*)d_in[0];   // k_space_input (B,1,320,320,2)
    float* out = (float*)d_out;                  // (B,1,2,320,320) float32
    (void)in_sizes; (void)n_in; (void)out_size;

    fused_rows_kernel<<<BATCH * RESN / NROWS, NROWS * LANES>>>(in);
    fft_cols_kernel  <<<BATCH * RESN / NROWS, NROWS * LANES>>>(out);
}

// round 7
// speedup vs baseline: 1.3274x; 1.1049x over previous
#include <cuda_runtime.h>

#define RESN  320
#define BATCH 32
#define HW    (RESN*RESN)

#define LANES  80
#define NROWS  8
#define SPITCH 321   // float2 pitch (pad to avoid bank conflicts on transposed access)

// Scratch (allocation-free rule: __device__ globals)
__device__ float2 g_tmp[BATCH*HW];   // 26 MB intermediate (after row FFTs, transposed)

// ---------------------------------------------------------------------------
// complex helpers
// ---------------------------------------------------------------------------
__device__ __forceinline__ float2 cadd(float2 a, float2 b){ return make_float2(a.x+b.x, a.y+b.y); }
__device__ __forceinline__ float2 csub(float2 a, float2 b){ return make_float2(a.x-b.x, a.y-b.y); }
__device__ __forceinline__ float2 cmul(float2 a, float2 b){
    return make_float2(a.x*b.x - a.y*b.y, a.x*b.y + a.y*b.x);
}
__device__ __forceinline__ float2 cjmul(float2 a){ return make_float2(-a.y, a.x); } // i*a

// Build 320-entry twiddle table: tw[k] = exp(+2*pi*i*k/320)
__device__ __forceinline__ void build_twiddle(float2* tw, int tid, int nthreads)
{
    for (int k = tid; k < RESN; k += nthreads) {
        float s, c;
        sincospif(2.0f * (float)k / (float)RESN, &s, &c);
        tw[k] = make_float2(c, s);
    }
}

// ---------------------------------------------------------------------------
// 320-point inverse (unnormalized) FFT, Stockham autosort, radices 5,4,4,4.
// Twiddles from shared table (exp(2pi*i*k/320)). Result natural order in A.
// ---------------------------------------------------------------------------
template<int Ns>
__device__ __forceinline__ void radix4_stage(const float2* __restrict__ src,
                                             float2* __restrict__ dst,
                                             const float2* __restrict__ tw, int j)
{
    float2 v0 = src[j];
    float2 v1 = src[j + 80];
    float2 v2 = src[j + 160];
    float2 v3 = src[j + 240];
    int m = j % Ns;
    constexpr int STEP = 80 / Ns;          // twiddle index step: m*STEP = m*320/(4Ns)
    float2 w1 = tw[m * STEP];
    float2 w2 = cmul(w1, w1);
    float2 w3 = cmul(w2, w1);
    v1 = cmul(v1, w1);
    v2 = cmul(v2, w2);
    v3 = cmul(v3, w3);
    float2 t0 = cadd(v0, v2), t1 = csub(v0, v2);
    float2 t2 = cadd(v1, v3), t3 = csub(v1, v3);
    float2 it3 = cjmul(t3);
    int d = (j / Ns) * (4 * Ns) + m;
    dst[d]          = cadd(t0, t2);
    dst[d + Ns]     = cadd(t1, it3);
    dst[d + 2 * Ns] = csub(t0, t2);
    dst[d + 3 * Ns] = csub(t1, it3);
}

__device__ __forceinline__ void fft320_inv(float2* A, float2* B,
                                           const float2* tw, int lane)
{
    // stage 1: radix-5, Ns=1, 64 butterflies, no twiddle. A -> B
    if (lane < 64) {
        float2 v0 = A[lane], v1 = A[lane+64], v2 = A[lane+128],
               v3 = A[lane+192], v4 = A[lane+256];
        const float c1 =  0.30901699437494745f, c2 = -0.80901699437494745f;
        const float s1 =  0.95105651629515353f, s2 =  0.58778525229247314f;
        float2 t1 = cadd(v1, v4), t2 = cadd(v2, v3);
        float2 t3 = csub(v1, v4), t4 = csub(v2, v3);
        float2 a1 = make_float2(v0.x + c1*t1.x + c2*t2.x, v0.y + c1*t1.y + c2*t2.y);
        float2 a2 = make_float2(v0.x + c2*t1.x + c1*t2.x, v0.y + c2*t1.y + c1*t2.y);
        float2 b1 = make_float2(s1*t3.x + s2*t4.x, s1*t3.y + s2*t4.y);
        float2 b2 = make_float2(s2*t3.x - s1*t4.x, s2*t3.y - s1*t4.y);
        float2 ib1 = cjmul(b1), ib2 = cjmul(b2);
        int d = lane * 5;
        B[d + 0] = make_float2(v0.x + t1.x + t2.x, v0.y + t1.y + t2.y);
        B[d + 1] = cadd(a1, ib1);
        B[d + 2] = cadd(a2, ib2);
        B[d + 3] = csub(a2, ib2);
        B[d + 4] = csub(a1, ib1);
    }
    __syncthreads();
    radix4_stage<5 >(B, A, tw, lane);  __syncthreads();
    radix4_stage<20>(A, B, tw, lane);  __syncthreads();
    radix4_stage<80>(B, A, tw, lane);  __syncthreads();
    // result in A, natural order
}

// ---------------------------------------------------------------------------
// Fused kernel: gridding stencil (separable, in smem) + row FFT + transposed
// store. Each block: batch b, 8 consecutive grid rows a0..a0+7.
// ---------------------------------------------------------------------------
__global__ __launch_bounds__(NROWS*LANES) void fused_rows_kernel(const float2* __restrict__ in)
{
    __shared__ float2 sA[NROWS * SPITCH];   // rowcomb -> grid rows -> FFT in/out
    __shared__ float2 sB[10 * SPITCH];      // input rows, later FFT scratch
    __shared__ float2 sTw[RESN];            // twiddle table
    int tid  = threadIdx.x;
    int rl   = tid / LANES;
    int lane = tid - rl * LANES;
    int b  = blockIdx.x / (RESN / NROWS);
    int a0 = (blockIdx.x % (RESN / NROWS)) * NROWS;
    const float2* cb = in + (size_t)b * HW;

    build_twiddle(sTw, tid, NROWS * LANES);

    // 1. load 10 input rows (iy = a0-1 .. a0+8), zero-padded at edges
    for (int i = tid; i < 10 * RESN; i += NROWS * LANES) {
        int r = i / RESN, col = i - r * RESN;
        int iy = a0 - 1 + r;
        float2 v = (iy >= 0 && iy < RESN) ? __ldg(&cb[iy * RESN + col])
                                          : make_float2(0.f, 0.f);
        sB[r * SPITCH + col] = v;
    }
    __syncthreads();

    // 2. vertical pass: rowcomb[a][i] = jm(a)*(row[a-1]+row[a]) + jm(a+1)*(row[a]+row[a+1])
    int a = a0 + rl;
    float c0 = (a >= 120 && a <= 160) ? 0.f : 1.f;                            // jm(a)
    float c1 = (a + 1 <= 319 && !(a + 1 >= 120 && a + 1 <= 160)) ? 1.f : 0.f; // jm(a+1)
    float c01 = c0 + c1;
    const float2* r0 = sB + rl * SPITCH;        // iy = a-1
    const float2* r1 = r0 + SPITCH;             // iy = a
    const float2* r2 = r1 + SPITCH;             // iy = a+1
    float2* A = sA + rl * SPITCH;
    #pragma unroll
    for (int k = 0; k < 4; ++k) {
        int i = lane + 80 * k;
        float2 v;
        v.x = c0 * r0[i].x + c01 * r1[i].x + c1 * r2[i].x;
        v.y = c0 * r0[i].y + c01 * r1[i].y + c1 * r2[i].y;
        A[i] = v;
    }
    __syncthreads();

    // 3. horizontal pass (read into regs, sync, write back — avoids RAW hazard)
    float2 vals[4];
    #pragma unroll
    for (int k = 0; k < 4; ++k) {
        int bx = lane + 80 * k;
        float2 rc  = A[bx];
        float2 rcm = (bx > 0)   ? A[bx - 1] : make_float2(0.f, 0.f);
        float2 rcp = (bx < 319) ? A[bx + 1] : make_float2(0.f, 0.f);
        float w0 = (bx >= 140 && bx <= 170) ? 0.f : 1.f;                      // im(bx)
        float w1 = (bx + 1 <= 319 && !(bx + 1 >= 140 && bx + 1 <= 170)) ? 1.f : 0.f;
        float vx = w0 * (rcm.x + rc.x) + w1 * (rc.x + rcp.x);
        float vy = w0 * (rcm.y + rc.y) + w1 * (rc.y + rcp.y);
        if (a0 == 0 && rl == 0 && bx == 0) {
            // all 21769 skipped trajectory points hit corner (0,0), weight 1/16
            float2 c00 = sB[1 * SPITCH + 0];   // input row iy=0, col 0
            vx += 21769.f * c00.x;
            vy += 21769.f * c00.y;
        }
        float s = ((a + bx) & 1) ? -0.0625f : 0.0625f;   // ifftshift pre-twist + 1/16
        vals[k] = make_float2(vx * s, vy * s);
    }
    __syncthreads();
    #pragma unroll
    for (int k = 0; k < 4; ++k) A[lane + 80 * k] = vals[k];
    __syncthreads();

    // 4. row FFT (sB rows reused as scratch — input no longer needed)
    fft320_inv(A, sB + rl * SPITCH, sTw, lane);

    // 5. transposed store: g_tmp[b][n][m]
    for (int i = tid; i < NROWS * RESN; i += NROWS * LANES) {
        int n  = i >> 3;
        int ml = i & 7;
        g_tmp[((size_t)b * RESN + n) * RESN + a0 + ml] = sA[ml * SPITCH + n];
    }
}

// ---------------------------------------------------------------------------
// Column FFTs (rows of g_tmp), fftshift post-twist (-1)^(m+n), planar output.
// ---------------------------------------------------------------------------
__global__ __launch_bounds__(NROWS*LANES) void fft_cols_kernel(float* __restrict__ out)
{
    __shared__ float2 sA[NROWS * SPITCH];
    __shared__ float2 sB[NROWS * SPITCH];
    __shared__ float2 sTw[RESN];
    int tid  = threadIdx.x;
    int rl   = tid / LANES;
    int lane = tid - rl * LANES;
    int rowg = blockIdx.x * NROWS + rl;         // = b*320 + n
    const float2* p = g_tmp + (size_t)rowg * RESN;
    float2* A = sA + rl * SPITCH;
    float2* B = sB + rl * SPITCH;

    build_twiddle(sTw, tid, NROWS * LANES);

    #pragma unroll
    for (int k = 0; k < 4; ++k) A[lane + 80*k] = p[lane + 80*k];
    __syncthreads();
    fft320_inv(A, B, sTw, lane);
    int b  = (blockIdx.x * NROWS) / RESN;
    int n0 = (blockIdx.x * NROWS) % RESN;
    float* outb = out + (size_t)b * 2 * HW;
    for (int i = tid; i < NROWS * RESN; i += NROWS * LANES) {
        int m  = i >> 3;
        int nl = i & 7;
        float2 v = sA[nl * SPITCH + m];
        float sg = ((m + n0 + nl) & 1) ? -1.0f : 1.0f;
        outb[m * RESN + n0 + nl]      = v.x * sg;   // real plane
        outb[HW + m * RESN + n0 + nl] = v.y * sg;   // imag plane
    }
}

// ---------------------------------------------------------------------------
extern "C" void kernel_launch(void* const* d_in, const int* in_sizes, int n_in,
                              void* d_out, int out_size)
{
    const float2* in = (const float2*)d_in[0];   // k_space_input (B,1,320,320,2)
    float* out = (float*)d_out;                  // (B,1,2,320,320) float32
    (void)in_sizes; (void)n_in; (void)out_size;

    fused_rows_kernel<<<BATCH * RESN / NROWS, NROWS * LANES>>>(in);
    fft_cols_kernel  <<<BATCH * RESN / NROWS, NROWS * LANES>>>(out);
}